// round 1
// baseline (speedup 1.0000x reference)
#include <cuda_runtime.h>

// Inv1x1MM_SVD: per position (B*T = 65536), C = 16.
//   ls = paras[:16]; U = paras[16:272] row-major 16x16; V = paras[272:528].
//   Q0 = qr(U).Q (positive-diag-R convention), Q1 = qr(V).Q
//   v_j = sum_c data_c * Q0[c,j];  w_j = v_j * exp(ls_j)
//   res_d = sum_j w_j * Q1[d,j]
//
// Layout: 16 lanes per position, lane j owns column j of the matrix in
// registers. MGS with deferred normalization; all cross-lane traffic via
// width-16 shuffles. Final product via register reduce-scatter.

constexpr int NPOS = 8 * 8192;
constexpr int PSTRIDE = 16 + 2 * 16 * 16;  // 528

__device__ __forceinline__ void mgs16(float (&c)[16], int j) {
    // Modified Gram-Schmidt, columns distributed one per lane (width-16 group).
    // Deferred normalization: columns kept unnormalized during the sweep,
    // projections use d/||q||^2; normalize once at the end.
    #pragma unroll 1
    for (int k = 0; k < 15; k++) {
        float nrm = 0.f;
        #pragma unroll
        for (int i = 0; i < 16; i++) nrm = fmaf(c[i], c[i], nrm);
        float qn = __shfl_sync(0xffffffffu, nrm, k, 16);  // ||c_k||^2
        float q[16];
        float d = 0.f;
        #pragma unroll
        for (int i = 0; i < 16; i++) {
            q[i] = __shfl_sync(0xffffffffu, c[i], k, 16);  // column k
            d = fmaf(q[i], c[i], d);                        // <c_k, c_j>
        }
        float scale = (j > k) ? __fdividef(d, qn) : 0.f;
        #pragma unroll
        for (int i = 0; i < 16; i++) c[i] = fmaf(-scale, q[i], c[i]);
    }
    float nrm = 0.f;
    #pragma unroll
    for (int i = 0; i < 16; i++) nrm = fmaf(c[i], c[i], nrm);
    float inv = rsqrtf(nrm);
    #pragma unroll
    for (int i = 0; i < 16; i++) c[i] *= inv;
}

__global__ void __launch_bounds__(256)
inv1x1mm_svd_kernel(const float* __restrict__ data,
                    const float* __restrict__ paras,
                    float* __restrict__ out) {
    const int gtid = blockIdx.x * 256 + threadIdx.x;
    const int warp = gtid >> 5;
    const int lane = gtid & 31;
    const int j = lane & 15;                 // column / element index
    const int pos = (warp << 1) | (lane >> 4);  // 2 positions per warp

    const float* p = paras + (size_t)pos * PSTRIDE;

    // Per-lane scalars
    const float dval = __ldg(&data[pos * 16 + j]);  // data_j
    const float ls   = __ldg(&p[j]);                // log-scale_j

    // ---- QR of U: lane j loads column j (U[i][j] = p[16 + i*16 + j]) ----
    float c0[16];
    #pragma unroll
    for (int i = 0; i < 16; i++) c0[i] = __ldg(&p[16 + i * 16 + j]);
    mgs16(c0, j);

    // v_j = sum_i data_i * Q0[i][j]  (broadcast data across the 16-lane group)
    float v = 0.f;
    #pragma unroll
    for (int i = 0; i < 16; i++)
        v = fmaf(__shfl_sync(0xffffffffu, dval, i, 16), c0[i], v);
    const float w = v * __expf(ls);

    // ---- QR of V (reuse registers) ----
    #pragma unroll
    for (int i = 0; i < 16; i++) c0[i] = __ldg(&p[16 + 256 + i * 16 + j]);
    mgs16(c0, j);

    // res = sum_j w_j * Q1col_j : cross-lane weighted vector sum.
    // Register reduce-scatter: after 4 stages lane j holds res_j in a[0].
    float a[16];
    #pragma unroll
    for (int i = 0; i < 16; i++) a[i] = w * c0[i];

    #pragma unroll
    for (int off = 8; off >= 1; off >>= 1) {
        const bool hi = (j & off) != 0;
        float s[8], o[8];
        #pragma unroll
        for (int i = 0; i < off; i++) {
            s[i] = hi ? a[i + off] : a[i];  // my contribution to my kept half
            o[i] = hi ? a[i] : a[i + off];  // my contribution to partner's half
        }
        #pragma unroll
        for (int i = 0; i < off; i++)
            a[i] = s[i] + __shfl_xor_sync(0xffffffffu, o[i], off, 16);
    }

    out[pos * 16 + j] = a[0];
}

extern "C" void kernel_launch(void* const* d_in, const int* in_sizes, int n_in,
                              void* d_out, int out_size) {
    const float* data  = (const float*)d_in[0];
    const float* paras = (const float*)d_in[1];
    // Defensive: identify by element count (data = 1,048,576; paras = 34,603,008)
    if (n_in >= 2 && in_sizes[0] > in_sizes[1]) {
        data  = (const float*)d_in[1];
        paras = (const float*)d_in[0];
    }
    // 2 positions per warp -> 32768 warps -> 1,048,576 threads -> 4096 blocks @256
    const int threads = 256;
    const int blocks  = (NPOS / 2) * 32 / threads;
    inv1x1mm_svd_kernel<<<blocks, threads>>>(data, paras, (float*)d_out);
}